// round 2
// baseline (speedup 1.0000x reference)
#include <cuda_runtime.h>

#define Tn  512
#define Bn  1024
#define Sn  64
#define An  16
#define Hn  128
#define TBn (Tn*Bn)

typedef unsigned long long ull;

// Scratch (allocation-free rule: __device__ globals)
__device__ float g_gx[(size_t)TBn * 384];      // x-side gate preactivations [T*B, 3H]
__device__ float g_hidden[(size_t)TBn * Hn];   // GRU hidden states [T*B, H]

// ---------------------------------------------------------------------------
// f32x2 packed-FMA helpers (FFMA2 is only reachable via PTX fma.rn.f32x2)
// ---------------------------------------------------------------------------
__device__ __forceinline__ ull pack2(float lo, float hi) {
    ull r;
    asm("mov.b64 %0, {%1, %2};" : "=l"(r)
        : "r"(__float_as_uint(lo)), "r"(__float_as_uint(hi)));
    return r;
}
__device__ __forceinline__ ull dup2(float v) { return pack2(v, v); }
__device__ __forceinline__ void unpack2(ull p, float& lo, float& hi) {
    unsigned int a, b;
    asm("mov.b64 {%0, %1}, %2;" : "=r"(a), "=r"(b) : "l"(p));
    lo = __uint_as_float(a); hi = __uint_as_float(b);
}
__device__ __forceinline__ void fma2(ull& d, ull a, ull b) {
    asm("fma.rn.f32x2 %0, %1, %2, %3;" : "=l"(d) : "l"(a), "l"(b), "l"(d));
}

__device__ __forceinline__ float sigmoidf_(float v) {
    float e = __expf(-v);
    return __fdividef(1.f, 1.f + e);
}
__device__ __forceinline__ float tanhf_(float v) {
    float e2 = __expf(-2.f * v);
    return (1.f - e2) * __fdividef(1.f, 1.f + e2);
}

// ---------------------------------------------------------------------------
// Encoder: fused  x -> h1 -> h2 -> gx.  256 threads, 64 rows/block.
// warp owns rows warp*8..+7 ; lane owns cols lane*4..+3 of a 128-col stripe.
// aT[k][row] stride 68 (LDS.128 broadcast -> two f32x2 row-pairs, pre-packed)
// WT[k][col] stride 132 (LDS.128 -> 4 cols), FFMA2 8x4 microtile.
// ---------------------------------------------------------------------------
#define EST_A 68
#define EST_W 132

template<int K>
__device__ __forceinline__ void gemm_tile(const float* __restrict__ aT,
                                          const float* __restrict__ wT,
                                          int warp, int lane, ull acc[4][4])
{
    const float* ap = aT + warp * 8;
    const float* wp = wT + lane * 4;
    #pragma unroll 4
    for (int k = 0; k < K; k++) {
        ulonglong2 a01 = *(const ulonglong2*)(ap + k * EST_A);      // rows (0,1),(2,3)
        ulonglong2 a23 = *(const ulonglong2*)(ap + k * EST_A + 4);  // rows (4,5),(6,7)
        float4 wv = *(const float4*)(wp + k * EST_W);
        ull w[4];
        w[0] = dup2(wv.x); w[1] = dup2(wv.y); w[2] = dup2(wv.z); w[3] = dup2(wv.w);
        #pragma unroll
        for (int c = 0; c < 4; c++) {
            fma2(acc[0][c], a01.x, w[c]);
            fma2(acc[1][c], a01.y, w[c]);
            fma2(acc[2][c], a23.x, w[c]);
            fma2(acc[3][c], a23.y, w[c]);
        }
    }
}

__device__ __forceinline__ void init_acc(ull acc[4][4], const float* __restrict__ b, int j0)
{
    #pragma unroll
    for (int c = 0; c < 4; c++) {
        ull bb = dup2(b[j0 + c]);
        #pragma unroll
        for (int p = 0; p < 4; p++) acc[p][c] = bb;
    }
}

__device__ __forceinline__ void store_act_relu(float* __restrict__ dst,
                                               int warp, int lane, ull acc[4][4])
{
    #pragma unroll
    for (int c = 0; c < 4; c++) {
        float v[8];
        unpack2(acc[0][c], v[0], v[1]); unpack2(acc[1][c], v[2], v[3]);
        unpack2(acc[2][c], v[4], v[5]); unpack2(acc[3][c], v[6], v[7]);
        #pragma unroll
        for (int i = 0; i < 8; i++) v[i] = fmaxf(v[i], 0.f);
        int col = lane * 4 + c;
        float4 lo = make_float4(v[0], v[1], v[2], v[3]);
        float4 hi = make_float4(v[4], v[5], v[6], v[7]);
        *(float4*)&dst[col * EST_A + warp * 8]     = lo;
        *(float4*)&dst[col * EST_A + warp * 8 + 4] = hi;
    }
}

__global__ void __launch_bounds__(256, 1) encoder_kernel(
    const float* __restrict__ x,
    const float* __restrict__ W1, const float* __restrict__ b1,
    const float* __restrict__ W2, const float* __restrict__ b2,
    const float* __restrict__ Wih, const float* __restrict__ bih)
{
    extern __shared__ float sm[];
    float* Wt  = sm;                    // 128*132 = 16896 floats
    float* h1T = sm + 128 * EST_W;      // 128*68  =  8704 floats
    float* h2T = h1T + 128 * EST_A;     // 128*68  (aliases xT)
    float* xT  = h2T;                   // 64*68 fits inside h2T region

    int tid  = threadIdx.x;
    int lane = tid & 31;
    int warp = tid >> 5;
    int base = blockIdx.x * 64;

    // ---- stage x (transposed) + W1 (transposed) ----
    for (int idx = tid; idx < 64 * 64; idx += 256) {
        int k = idx & 63, r = idx >> 6;
        xT[k * EST_A + r] = x[(base + r) * 64 + k];
    }
    for (int idx = tid; idx < 128 * 64; idx += 256) {
        int k = idx & 63, j = idx >> 6;
        Wt[k * EST_W + j] = W1[j * 64 + k];
    }
    __syncthreads();

    ull acc[4][4];

    // ---- Phase A: h1 = relu(x @ W1^T + b1) ----
    init_acc(acc, b1, lane * 4);
    gemm_tile<64>(xT, Wt, warp, lane, acc);
    store_act_relu(h1T, warp, lane, acc);
    __syncthreads();

    // ---- Phase B: h2 = relu(h1 @ W2^T + b2) ----
    for (int idx = tid; idx < 128 * 128; idx += 256) {
        int k = idx & 127, j = idx >> 7;
        Wt[k * EST_W + j] = W2[j * 128 + k];
    }
    __syncthreads();
    init_acc(acc, b2, lane * 4);
    gemm_tile<128>(h1T, Wt, warp, lane, acc);
    store_act_relu(h2T, warp, lane, acc);   // xT dead (only read before 2 barriers)
    __syncthreads();

    // ---- Phase C: gx = h2 @ Wih^T + bih, in 3 column passes of 128 ----
    for (int pp = 0; pp < 3; pp++) {
        for (int idx = tid; idx < 128 * 128; idx += 256) {
            int k = idx & 127, j = idx >> 7;
            Wt[k * EST_W + j] = Wih[(pp * 128 + j) * 128 + k];
        }
        __syncthreads();
        init_acc(acc, bih, pp * 128 + lane * 4);
        gemm_tile<128>(h2T, Wt, warp, lane, acc);

        float v[8][4];
        #pragma unroll
        for (int p = 0; p < 4; p++)
            #pragma unroll
            for (int c = 0; c < 4; c++)
                unpack2(acc[p][c], v[2 * p][c], v[2 * p + 1][c]);
        #pragma unroll
        for (int rr = 0; rr < 8; rr++) {
            size_t row = (size_t)(base + warp * 8 + rr);
            float4 o = make_float4(v[rr][0], v[rr][1], v[rr][2], v[rr][3]);
            *(float4*)&g_gx[row * 384 + pp * 128 + lane * 4] = o;
        }
        __syncthreads();   // Wt reads done before next pass overwrites
    }
}

// ---------------------------------------------------------------------------
// GRU scan: 128 blocks x 8 batch rows, 256 threads (thread = col c, half = 4 rows).
// Whh resident in smem (stride-385 planes). h transposed + double-buffered:
// hb[buf][k*12 + r] -> LDS.128 broadcast gives 4 rows as two pre-packed f32x2.
// One __syncthreads per step; next-step gx + done prefetched over the k-loop.
// ---------------------------------------------------------------------------
__global__ void __launch_bounds__(256, 1) scan_kernel(
    const float* __restrict__ done, const float* __restrict__ gru0,
    const float* __restrict__ Whh, const float* __restrict__ bhh,
    float* __restrict__ out)
{
    extern __shared__ float sm[];
    float* wsm = sm;                 // [k*385 + j], j = c + 128*gate
    float* hb  = sm + 128 * 385;     // 2 buffers of 128*12 floats

    int tid  = threadIdx.x;
    int c    = tid & 127;
    int half = tid >> 7;
    int r0   = half * 4;
    int b0   = blockIdx.x << 3;

    // weights transposed: wsm[k][j]  (store: lanes stride 385 -> conflict-free)
    for (int idx = tid; idx < 384 * 128; idx += 256) {
        int k = idx & 127, j = idx >> 7;
        wsm[k * 385 + j] = Whh[j * 128 + k];
    }
    // initial h (t=0 done-mask folded in), transposed layout
    #pragma unroll
    for (int i = 0; i < 4; i++) {
        int r = r0 + i;
        hb[c * 12 + r] = gru0[(b0 + r) * 128 + c] * (1.f - done[b0 + r]);
    }
    __syncthreads();

    float br = bhh[c], bz = bhh[c + 128], bn = bhh[c + 256];

    float gr[4], gz[4], gn[4];
    #pragma unroll
    for (int i = 0; i < 4; i++) {
        size_t row = (size_t)(b0 + r0 + i);
        gr[i] = g_gx[row * 384 + c];
        gz[i] = g_gx[row * 384 + 128 + c];
        gn[i] = g_gx[row * 384 + 256 + c];
    }

    int cur = 0;
    for (int t = 0; t < Tn; t++) {
        ull aR0 = pack2(br + gr[0], br + gr[1]), aR1 = pack2(br + gr[2], br + gr[3]);
        ull aZ0 = pack2(bz + gz[0], bz + gz[1]), aZ1 = pack2(bz + gz[2], bz + gz[3]);
        ull aN0 = dup2(bn), aN1 = dup2(bn);
        float gnl[4];
        #pragma unroll
        for (int i = 0; i < 4; i++) gnl[i] = gn[i];

        // prefetch next step's gx + done (hidden under the k-loop)
        int tn = (t + 1 < Tn) ? (t + 1) : t;
        #pragma unroll
        for (int i = 0; i < 4; i++) {
            size_t row = (size_t)tn * Bn + b0 + r0 + i;
            gr[i] = g_gx[row * 384 + c];
            gz[i] = g_gx[row * 384 + 128 + c];
            gn[i] = g_gx[row * 384 + 256 + c];
        }
        float dnx[4];
        #pragma unroll
        for (int i = 0; i < 4; i++)
            dnx[i] = (t + 1 < Tn) ? done[(size_t)(t + 1) * Bn + b0 + r0 + i] : 0.f;

        const float* hbc = hb + cur * 1536;
        float hold[4];
        #pragma unroll
        for (int i = 0; i < 4; i++) hold[i] = hbc[c * 12 + r0 + i];

        #pragma unroll 4
        for (int k = 0; k < 128; k++) {
            ulonglong2 hp = *(const ulonglong2*)&hbc[k * 12 + r0];  // broadcast
            float wr = wsm[k * 385 + c];
            float wz = wsm[k * 385 + 128 + c];
            float wn = wsm[k * 385 + 256 + c];
            ull wr2 = dup2(wr), wz2 = dup2(wz), wn2 = dup2(wn);
            fma2(aR0, hp.x, wr2); fma2(aR1, hp.y, wr2);
            fma2(aZ0, hp.x, wz2); fma2(aZ1, hp.y, wz2);
            fma2(aN0, hp.x, wn2); fma2(aN1, hp.y, wn2);
        }

        float arv[4], azv[4], anv[4];
        unpack2(aR0, arv[0], arv[1]); unpack2(aR1, arv[2], arv[3]);
        unpack2(aZ0, azv[0], azv[1]); unpack2(aZ1, azv[2], azv[3]);
        unpack2(aN0, anv[0], anv[1]); unpack2(aN1, anv[2], anv[3]);

        float hn4[4];
        #pragma unroll
        for (int i = 0; i < 4; i++) {
            float r  = sigmoidf_(arv[i]);
            float z  = sigmoidf_(azv[i]);
            float th = tanhf_(gnl[i] + r * anv[i]);
            hn4[i] = (1.f - z) * th + z * hold[i];
            g_hidden[((size_t)t * Bn + b0 + r0 + i) * Hn + c] = hn4[i];
        }
        if (t == Tn - 1) {
            #pragma unroll
            for (int i = 0; i < 4; i++)
                out[(size_t)TBn * 3 + (b0 + r0 + i) * Hn + c] = hn4[i];
        }

        int nxt = cur ^ 1;
        float4 st = make_float4(hn4[0] * (1.f - dnx[0]), hn4[1] * (1.f - dnx[1]),
                                hn4[2] * (1.f - dnx[2]), hn4[3] * (1.f - dnx[3]));
        *(float4*)&hb[nxt * 1536 + c * 12 + r0] = st;
        __syncthreads();
        cur = nxt;
    }
}

// ---------------------------------------------------------------------------
// Heads: 256 rows/block, thread-per-row.
// ---------------------------------------------------------------------------
__global__ void __launch_bounds__(256, 1) heads_kernel(
    const int* __restrict__ action,
    const float* __restrict__ Wa, const float* __restrict__ ba,
    const float* __restrict__ Wc, const float* __restrict__ bc,
    float* __restrict__ out)
{
    extern __shared__ float sm[];
    const int OFF_WA = 256 * 129;
    const int OFF_WC = OFF_WA + 16 * 128;
    int tid  = threadIdx.x;
    int base = blockIdx.x << 8;

    for (int idx = tid; idx < 256 * 128; idx += 256) {
        int r = idx >> 7, k = idx & 127;
        sm[r * 129 + k] = g_hidden[(size_t)(base + r) * 128 + k];
    }
    for (int idx = tid; idx < 16 * 128; idx += 256) sm[OFF_WA + idx] = Wa[idx];
    if (tid < 128) sm[OFF_WC + tid] = Wc[tid];
    __syncthreads();

    float l[16];
    #pragma unroll
    for (int j = 0; j < 16; j++) l[j] = ba[j];
    float v = bc[0];
    const float* hrow = &sm[tid * 129];
    #pragma unroll 4
    for (int k = 0; k < 128; k++) {
        float hv = hrow[k];
        #pragma unroll
        for (int j = 0; j < 16; j++) l[j] += sm[OFF_WA + j * 128 + k] * hv;
        v += sm[OFF_WC + k] * hv;
    }
    float mx = l[0];
    #pragma unroll
    for (int j = 1; j < 16; j++) mx = fmaxf(mx, l[j]);
    float se = 0.f, pl = 0.f;
    #pragma unroll
    for (int j = 0; j < 16; j++) {
        float e = __expf(l[j] - mx);
        se += e; pl += e * l[j];
    }
    float lse = mx + __logf(se);
    int row = base + tid;
    int a = action[row];
    float la = 0.f;
    #pragma unroll
    for (int j = 0; j < 16; j++) la = (a == j) ? l[j] : la;
    out[(size_t)row * 3 + 0] = la - lse;
    out[(size_t)row * 3 + 1] = lse - pl / se;
    out[(size_t)row * 3 + 2] = v;
}

// ---------------------------------------------------------------------------
extern "C" void kernel_launch(void* const* d_in, const int* in_sizes, int n_in,
                              void* d_out, int out_size)
{
    const float* x    = (const float*)d_in[0];
    const float* done = (const float*)d_in[1];
    const int*   act  = (const int*)  d_in[2];
    const float* gru  = (const float*)d_in[3];
    const float* W1   = (const float*)d_in[4];
    const float* b1   = (const float*)d_in[5];
    const float* W2   = (const float*)d_in[6];
    const float* b2   = (const float*)d_in[7];
    const float* Wih  = (const float*)d_in[8];
    const float* bih  = (const float*)d_in[9];
    const float* Whh  = (const float*)d_in[10];
    const float* bhh  = (const float*)d_in[11];
    const float* Wa   = (const float*)d_in[12];
    const float* ba   = (const float*)d_in[13];
    const float* Wc   = (const float*)d_in[14];
    const float* bc   = (const float*)d_in[15];
    float* out = (float*)d_out;

    size_t enc_smem  = (size_t)(128 * EST_W + 2 * 128 * EST_A) * sizeof(float); // 137216 B
    size_t scan_smem = (size_t)(128 * 385 + 2 * 128 * 12) * sizeof(float);      // 209408 B
    size_t head_smem = (size_t)(256 * 129 + 16 * 128 + 128) * sizeof(float);    // 140800 B

    cudaFuncSetAttribute(encoder_kernel, cudaFuncAttributeMaxDynamicSharedMemorySize, (int)enc_smem);
    cudaFuncSetAttribute(scan_kernel,    cudaFuncAttributeMaxDynamicSharedMemorySize, (int)scan_smem);
    cudaFuncSetAttribute(heads_kernel,   cudaFuncAttributeMaxDynamicSharedMemorySize, (int)head_smem);

    encoder_kernel<<<TBn / 64, 256, enc_smem>>>(x, W1, b1, W2, b2, Wih, bih);
    scan_kernel<<<128, 256, scan_smem>>>(done, gru, Whh, bhh, out);
    heads_kernel<<<TBn / 256, 256, head_smem>>>(act, Wa, ba, Wc, bc, out);
}

// round 3
// speedup vs baseline: 1.8770x; 1.8770x over previous
#include <cuda_runtime.h>

#define Tn  512
#define Bn  1024
#define Sn  64
#define An  16
#define Hn  128
#define TBn (Tn*Bn)

typedef unsigned long long ull;

__device__ float g_gx[(size_t)TBn * 384];      // x-side gate preactivations [T*B, 3H]
__device__ float g_hidden[(size_t)TBn * Hn];   // GRU hidden states [T*B, H]

// ---------------------------------------------------------------------------
// f32x2 helpers
// ---------------------------------------------------------------------------
__device__ __forceinline__ ull pack2(float lo, float hi) {
    ull r;
    asm("mov.b64 %0, {%1, %2};" : "=l"(r)
        : "r"(__float_as_uint(lo)), "r"(__float_as_uint(hi)));
    return r;
}
__device__ __forceinline__ ull dup2(float v) { return pack2(v, v); }
__device__ __forceinline__ void unpack2(ull p, float& lo, float& hi) {
    unsigned int a, b;
    asm("mov.b64 {%0, %1}, %2;" : "=r"(a), "=r"(b) : "l"(p));
    lo = __uint_as_float(a); hi = __uint_as_float(b);
}
__device__ __forceinline__ float hadd2(ull p) {
    float lo, hi; unpack2(p, lo, hi); return lo + hi;
}
__device__ __forceinline__ void fma2(ull& d, ull a, ull b) {
    asm("fma.rn.f32x2 %0, %1, %2, %3;" : "=l"(d) : "l"(a), "l"(b), "l"(d));
}

__device__ __forceinline__ float sigmoidf_(float v) {
    float e = __expf(-v);
    return __fdividef(1.f, 1.f + e);
}
__device__ __forceinline__ float tanhf_(float v) {
    float e2 = __expf(-2.f * v);
    return (1.f - e2) * __fdividef(1.f, 1.f + e2);
}

// ---------------------------------------------------------------------------
// Encoder: fused x -> h1 -> h2 -> gx.  512 threads, 64 rows/block, 2 blocks/SM.
// rg = tid>>6 owns rows rg*8..+7 ; cg = tid&63 owns cols 2cg,2cg+1.
// aT[k][row] stride 68; Wt[k][col] stride 130, streamed in 64-k chunks.
// ---------------------------------------------------------------------------
#define EA  68
#define EWs 130

__device__ __forceinline__ void gemm64(const float* __restrict__ ap,
                                       const float* __restrict__ wp,
                                       ull acc[4][2])
{
    #pragma unroll 4
    for (int k = 0; k < 64; k++) {
        ulonglong2 a01 = *(const ulonglong2*)(ap + k * EA);      // rows (0,1),(2,3)
        ulonglong2 a23 = *(const ulonglong2*)(ap + k * EA + 4);  // rows (4,5),(6,7)
        float2 wv = *(const float2*)(wp + k * EWs);
        ull w0 = dup2(wv.x), w1 = dup2(wv.y);
        fma2(acc[0][0], a01.x, w0); fma2(acc[1][0], a01.y, w0);
        fma2(acc[2][0], a23.x, w0); fma2(acc[3][0], a23.y, w0);
        fma2(acc[0][1], a01.x, w1); fma2(acc[1][1], a01.y, w1);
        fma2(acc[2][1], a23.x, w1); fma2(acc[3][1], a23.y, w1);
    }
}

__global__ void __launch_bounds__(512, 2) encoder_kernel(
    const float* __restrict__ x,
    const float* __restrict__ W1, const float* __restrict__ b1,
    const float* __restrict__ W2, const float* __restrict__ b2,
    const float* __restrict__ Wih, const float* __restrict__ bih)
{
    extern __shared__ float sm[];
    float* Wt  = sm;                    // 64*130  = 8320 floats
    float* h1T = sm + 64 * EWs;         // 128*68  = 8704 floats
    float* h2T = h1T + 128 * EA;        // 128*68
    float* xT  = h2T;                   // 64*68 aliased into h2T region

    int tid = threadIdx.x;
    int cg  = tid & 63;
    int rg  = tid >> 6;
    int base = blockIdx.x * 64;

    // stage xT (transposed) + W1 (transposed, K=64 fits one chunk)
    for (int idx = tid; idx < 64 * 64; idx += 512) {
        int k = idx & 63, r = idx >> 6;
        xT[k * EA + r] = x[(base + r) * 64 + k];
    }
    for (int idx = tid; idx < 64 * 128; idx += 512) {
        int k = idx & 63, j = idx >> 6;
        Wt[k * EWs + j] = W1[j * 64 + k];
    }
    __syncthreads();

    ull acc[4][2];
    const float* ap;

    // ---- Phase A: h1 = relu(x @ W1^T + b1) ----
    acc[0][0] = acc[1][0] = acc[2][0] = acc[3][0] = dup2(b1[2 * cg]);
    acc[0][1] = acc[1][1] = acc[2][1] = acc[3][1] = dup2(b1[2 * cg + 1]);
    gemm64(xT + rg * 8, Wt + 2 * cg, acc);
    // write h1T (relu)
    #pragma unroll
    for (int c01 = 0; c01 < 2; c01++) {
        float v[8];
        unpack2(acc[0][c01], v[0], v[1]); unpack2(acc[1][c01], v[2], v[3]);
        unpack2(acc[2][c01], v[4], v[5]); unpack2(acc[3][c01], v[6], v[7]);
        #pragma unroll
        for (int i = 0; i < 8; i++) v[i] = fmaxf(v[i], 0.f);
        int col = 2 * cg + c01;
        *(float4*)&h1T[col * EA + rg * 8]     = make_float4(v[0], v[1], v[2], v[3]);
        *(float4*)&h1T[col * EA + rg * 8 + 4] = make_float4(v[4], v[5], v[6], v[7]);
    }
    __syncthreads();

    // ---- Phase B: h2 = relu(h1 @ W2^T + b2), K=128 in 2 chunks ----
    acc[0][0] = acc[1][0] = acc[2][0] = acc[3][0] = dup2(b2[2 * cg]);
    acc[0][1] = acc[1][1] = acc[2][1] = acc[3][1] = dup2(b2[2 * cg + 1]);
    #pragma unroll 1
    for (int h = 0; h < 2; h++) {
        for (int idx = tid; idx < 64 * 128; idx += 512) {
            int kl = idx & 63, j = idx >> 6;
            Wt[kl * EWs + j] = W2[j * 128 + h * 64 + kl];
        }
        __syncthreads();
        gemm64(h1T + (h * 64) * EA + rg * 8, Wt + 2 * cg, acc);
        __syncthreads();
    }
    #pragma unroll
    for (int c01 = 0; c01 < 2; c01++) {
        float v[8];
        unpack2(acc[0][c01], v[0], v[1]); unpack2(acc[1][c01], v[2], v[3]);
        unpack2(acc[2][c01], v[4], v[5]); unpack2(acc[3][c01], v[6], v[7]);
        #pragma unroll
        for (int i = 0; i < 8; i++) v[i] = fmaxf(v[i], 0.f);
        int col = 2 * cg + c01;
        *(float4*)&h2T[col * EA + rg * 8]     = make_float4(v[0], v[1], v[2], v[3]);
        *(float4*)&h2T[col * EA + rg * 8 + 4] = make_float4(v[4], v[5], v[6], v[7]);
    }
    __syncthreads();

    // ---- Phase C: gx = h2 @ Wih^T + bih : 3 col passes x 2 k-chunks ----
    #pragma unroll 1
    for (int pp = 0; pp < 3; pp++) {
        acc[0][0] = acc[1][0] = acc[2][0] = acc[3][0] = dup2(bih[pp * 128 + 2 * cg]);
        acc[0][1] = acc[1][1] = acc[2][1] = acc[3][1] = dup2(bih[pp * 128 + 2 * cg + 1]);
        #pragma unroll 1
        for (int h = 0; h < 2; h++) {
            for (int idx = tid; idx < 64 * 128; idx += 512) {
                int kl = idx & 63, j = idx >> 6;
                Wt[kl * EWs + j] = Wih[(pp * 128 + j) * 128 + h * 64 + kl];
            }
            __syncthreads();
            gemm64(h2T + (h * 64) * EA + rg * 8, Wt + 2 * cg, acc);
            __syncthreads();
        }
        // store float2 per row to g_gx (coalesced 256B/warp)
        #pragma unroll
        for (int p = 0; p < 4; p++) {
            float v0a, v0b, v1a, v1b;
            unpack2(acc[p][0], v0a, v0b);
            unpack2(acc[p][1], v1a, v1b);
            size_t row0 = (size_t)(base + rg * 8 + 2 * p);
            *(float2*)&g_gx[row0 * 384 + pp * 128 + 2 * cg]       = make_float2(v0a, v1a);
            *(float2*)&g_gx[(row0 + 1) * 384 + pp * 128 + 2 * cg] = make_float2(v0b, v1b);
        }
    }
}

// ---------------------------------------------------------------------------
// GRU scan: 128 blocks x 8 batch rows, 128 threads (thread = col c, all 8 rows).
// wsm[gate][c][k] stride 132 (LDS.128 conflict-free); h double-buffered
// hT[r][feature] stride 132. k-packed FFMA2 accs (24 chains), 1 bar/step.
// ---------------------------------------------------------------------------
#define WS 132

__global__ void __launch_bounds__(128, 1) scan_kernel(
    const float* __restrict__ done, const float* __restrict__ gru0,
    const float* __restrict__ Whh, const float* __restrict__ bhh,
    float* __restrict__ out)
{
    extern __shared__ float sm[];
    float* wsm = sm;                       // 3 * 128 * 132
    float* hb  = sm + 3 * 128 * WS;        // 2 * 8 * 132

    int c  = threadIdx.x;                  // 0..127
    int b0 = blockIdx.x << 3;

    // stage Whh transposed-per-gate: wsm[g*128*WS + cc*WS + k]
    for (int idx = c; idx < 384 * 128; idx += 128) {
        int k = idx & 127, j = idx >> 7;
        int g = j >> 7, cc = j & 127;
        wsm[g * 128 * WS + cc * WS + k] = Whh[j * 128 + k];
    }
    // initial h with t=0 done-mask folded in
    #pragma unroll
    for (int r = 0; r < 8; r++)
        hb[r * WS + c] = gru0[(b0 + r) * 128 + c] * (1.f - done[b0 + r]);
    __syncthreads();

    float br = bhh[c], bz = bhh[c + 128], bn = bhh[c + 256];

    float gxc[8][3];
    #pragma unroll
    for (int r = 0; r < 8; r++) {
        size_t row = (size_t)(b0 + r);
        gxc[r][0] = g_gx[row * 384 + c];
        gxc[r][1] = g_gx[row * 384 + 128 + c];
        gxc[r][2] = g_gx[row * 384 + 256 + c];
    }

    const float* w0p = wsm + c * WS;
    const float* w1p = wsm + 128 * WS + c * WS;
    const float* w2p = wsm + 256 * WS + c * WS;

    int cur = 0;
    for (int t = 0; t < Tn; t++) {
        // prefetch next step's gx + done early (hidden under k-loop)
        float gxn[8][3], dn[8];
        int tnx = (t + 1 < Tn) ? (t + 1) : t;
        #pragma unroll
        for (int r = 0; r < 8; r++) {
            size_t row = (size_t)tnx * Bn + b0 + r;
            gxn[r][0] = g_gx[row * 384 + c];
            gxn[r][1] = g_gx[row * 384 + 128 + c];
            gxn[r][2] = g_gx[row * 384 + 256 + c];
            dn[r] = (t + 1 < Tn) ? done[(size_t)(t + 1) * Bn + b0 + r] : 0.f;
        }

        const float* hbc = hb + cur * (8 * WS);
        ull aR[8], aZ[8], aN[8];
        #pragma unroll
        for (int r = 0; r < 8; r++) { aR[r] = 0ull; aZ[r] = 0ull; aN[r] = 0ull; }

        #pragma unroll 2
        for (int k4 = 0; k4 < 32; k4++) {
            int k = k4 * 4;
            ulonglong2 wr = *(const ulonglong2*)(w0p + k);
            ulonglong2 wz = *(const ulonglong2*)(w1p + k);
            ulonglong2 wn = *(const ulonglong2*)(w2p + k);
            #pragma unroll
            for (int r = 0; r < 8; r++) {
                ulonglong2 hp = *(const ulonglong2*)(hbc + r * WS + k);  // broadcast
                fma2(aR[r], hp.x, wr.x); fma2(aR[r], hp.y, wr.y);
                fma2(aZ[r], hp.x, wz.x); fma2(aZ[r], hp.y, wz.y);
                fma2(aN[r], hp.x, wn.x); fma2(aN[r], hp.y, wn.y);
            }
        }

        float* hbn = hb + (cur ^ 1) * (8 * WS);
        #pragma unroll
        for (int r = 0; r < 8; r++) {
            float sr = hadd2(aR[r]) + br + gxc[r][0];
            float sz = hadd2(aZ[r]) + bz + gxc[r][1];
            float hn = hadd2(aN[r]) + bn;
            float rg_ = sigmoidf_(sr);
            float zg  = sigmoidf_(sz);
            float ng  = tanhf_(gxc[r][2] + rg_ * hn);
            float hold = hbc[r * WS + c];
            float hnew = (1.f - zg) * ng + zg * hold;
            g_hidden[((size_t)t * Bn + b0 + r) * Hn + c] = hnew;
            hbn[r * WS + c] = hnew * (1.f - dn[r]);
            if (t == Tn - 1)
                out[(size_t)TBn * 3 + (b0 + r) * Hn + c] = hnew;
            gxc[r][0] = gxn[r][0]; gxc[r][1] = gxn[r][1]; gxc[r][2] = gxn[r][2];
        }
        __syncthreads();
        cur ^= 1;
    }
}

// ---------------------------------------------------------------------------
// Heads: 256 rows/block, thread-per-row.
// ---------------------------------------------------------------------------
__global__ void __launch_bounds__(256, 1) heads_kernel(
    const int* __restrict__ action,
    const float* __restrict__ Wa, const float* __restrict__ ba,
    const float* __restrict__ Wc, const float* __restrict__ bc,
    float* __restrict__ out)
{
    extern __shared__ float sm[];
    const int OFF_WA = 256 * 129;
    const int OFF_WC = OFF_WA + 16 * 128;
    int tid  = threadIdx.x;
    int base = blockIdx.x << 8;

    for (int idx = tid; idx < 256 * 128; idx += 256) {
        int r = idx >> 7, k = idx & 127;
        sm[r * 129 + k] = g_hidden[(size_t)(base + r) * 128 + k];
    }
    for (int idx = tid; idx < 16 * 128; idx += 256) sm[OFF_WA + idx] = Wa[idx];
    if (tid < 128) sm[OFF_WC + tid] = Wc[tid];
    __syncthreads();

    float l[16];
    #pragma unroll
    for (int j = 0; j < 16; j++) l[j] = ba[j];
    float v = bc[0];
    const float* hrow = &sm[tid * 129];
    #pragma unroll 4
    for (int k = 0; k < 128; k++) {
        float hv = hrow[k];
        #pragma unroll
        for (int j = 0; j < 16; j++) l[j] += sm[OFF_WA + j * 128 + k] * hv;
        v += sm[OFF_WC + k] * hv;
    }
    float mx = l[0];
    #pragma unroll
    for (int j = 1; j < 16; j++) mx = fmaxf(mx, l[j]);
    float se = 0.f, pl = 0.f;
    #pragma unroll
    for (int j = 0; j < 16; j++) {
        float e = __expf(l[j] - mx);
        se += e; pl += e * l[j];
    }
    float lse = mx + __logf(se);
    int row = base + tid;
    int a = action[row];
    float la = 0.f;
    #pragma unroll
    for (int j = 0; j < 16; j++) la = (a == j) ? l[j] : la;
    out[(size_t)row * 3 + 0] = la - lse;
    out[(size_t)row * 3 + 1] = lse - pl / se;
    out[(size_t)row * 3 + 2] = v;
}

// ---------------------------------------------------------------------------
extern "C" void kernel_launch(void* const* d_in, const int* in_sizes, int n_in,
                              void* d_out, int out_size)
{
    const float* x    = (const float*)d_in[0];
    const float* done = (const float*)d_in[1];
    const int*   act  = (const int*)  d_in[2];
    const float* gru  = (const float*)d_in[3];
    const float* W1   = (const float*)d_in[4];
    const float* b1   = (const float*)d_in[5];
    const float* W2   = (const float*)d_in[6];
    const float* b2   = (const float*)d_in[7];
    const float* Wih  = (const float*)d_in[8];
    const float* bih  = (const float*)d_in[9];
    const float* Whh  = (const float*)d_in[10];
    const float* bhh  = (const float*)d_in[11];
    const float* Wa   = (const float*)d_in[12];
    const float* ba   = (const float*)d_in[13];
    const float* Wc   = (const float*)d_in[14];
    const float* bc   = (const float*)d_in[15];
    float* out = (float*)d_out;

    size_t enc_smem  = (size_t)(64 * EWs + 2 * 128 * EA) * sizeof(float);        // 102912 B
    size_t scan_smem = (size_t)(3 * 128 * WS + 2 * 8 * WS) * sizeof(float);      // 211200 B
    size_t head_smem = (size_t)(256 * 129 + 16 * 128 + 128) * sizeof(float);     // 140800 B

    cudaFuncSetAttribute(encoder_kernel, cudaFuncAttributeMaxDynamicSharedMemorySize, (int)enc_smem);
    cudaFuncSetAttribute(scan_kernel,    cudaFuncAttributeMaxDynamicSharedMemorySize, (int)scan_smem);
    cudaFuncSetAttribute(heads_kernel,   cudaFuncAttributeMaxDynamicSharedMemorySize, (int)head_smem);

    encoder_kernel<<<TBn / 64, 512, enc_smem>>>(x, W1, b1, W2, b2, Wih, bih);
    scan_kernel<<<128, 128, scan_smem>>>(done, gru, Whh, bhh, out);
    heads_kernel<<<TBn / 256, 256, head_smem>>>(act, Wa, ba, Wc, bc, out);
}